// round 7
// baseline (speedup 1.0000x reference)
#include <cuda_runtime.h>
#include <cuda_bf16.h>

#define OUT_SZ 7
#define NCELL (OUT_SZ * OUT_SZ)      // 49
#define NCH 256
#define NQ (NCH / 4)                 // 64 float4 per channel row
#define SLOTS 8                      // cell slots per block
#define NTHREADS (NQ * SLOTS)        // 512

__global__ __launch_bounds__(NTHREADS, 3)
void roialign_kernel(const float* __restrict__ p2,
                     const float* __restrict__ p3,
                     const float* __restrict__ p4,
                     const float* __restrict__ p5,
                     const float* __restrict__ rois,
                     float* __restrict__ out)
{
    int roi  = blockIdx.x;
    int tid  = threadIdx.x;
    int cq   = tid & (NQ - 1);       // channel quad 0..63
    int slot = tid >> 6;             // 0..7

    // ---- per-thread ROI decode (once; amortized over ~6 cells) ----
    const float* r = rois + (size_t)roi * 5;   // [batch, x1, y1, x2, y2]
    float bf  = __ldg(r + 0);
    float rx1 = __ldg(r + 1), ry1 = __ldg(r + 2);
    float rx2 = __ldg(r + 3), ry2 = __ldg(r + 4);
    int b = (int)bf;

    float roi_w = rx2 - rx1;
    float roi_h = ry2 - ry1;
    float lvl = 4.0f + log2f(sqrtf(roi_h * roi_w) / 224.0f);
    int level = (int)rintf(lvl);
    level = level < 2 ? 2 : (level > 5 ? 5 : level);

    const float* fm;
    int H;
    float inv_stride;
    switch (level) {
        case 2: fm = p2; H = 256; inv_stride = 1.0f / 4.0f;  break;
        case 3: fm = p3; H = 128; inv_stride = 1.0f / 8.0f;  break;
        case 4: fm = p4; H = 64;  inv_stride = 1.0f / 16.0f; break;
        default: fm = p5; H = 32; inv_stride = 1.0f / 32.0f; break;
    }
    float Hm1 = (float)(H - 1);
    int   Hm1i = H - 1;
    int   rowstride = H * NQ;        // float4 per feature-map row

    // crop_and_resize reads boxes as [y1,x1,y2,x2]; roi_align passes
    // [x1,y1,x2,y2]*(1/stride). So box_y1 = rx1/stride, box_x1 = ry1/stride.
    float by1 = rx1 * inv_stride;
    float bx1 = ry1 * inv_stride;
    float by2 = rx2 * inv_stride;
    float bx2 = ry2 * inv_stride;

    float h_scale = (by2 - by1) * Hm1 * (1.0f / (float)(OUT_SZ - 1));
    float w_scale = (bx2 - bx1) * Hm1 * (1.0f / (float)(OUT_SZ - 1));
    float y_base = by1 * Hm1;
    float x_base = bx1 * Hm1;

    const float4* fm_b = (const float4*)(fm + (size_t)b * H * H * NCH);
    float4* out_roi = (float4*)(out + (size_t)roi * NCELL * NCH);

    // slot -> initial (i, j); slots 0..6 are row 0, slot 7 is (1,0)
    int i = slot >= OUT_SZ ? 1 : 0;
    int j = slot >= OUT_SZ ? slot - OUT_SZ : slot;

#pragma unroll 1
    for (int cell = slot; cell < NCELL; cell += SLOTS) {
        float in_y = fmaf((float)i, h_scale, y_base);
        float in_x = fmaf((float)j, w_scale, x_base);
        bool valid = (in_y >= 0.0f) & (in_y <= Hm1) &
                     (in_x >= 0.0f) & (in_x <= Hm1);

        float fy = floorf(in_y);
        float fx = floorf(in_x);
        float ly = in_y - fy;
        float lx = in_x - fx;
        int y0 = min(max((int)fy, 0), Hm1i);
        int x0 = min(max((int)fx, 0), Hm1i);
        int yc = (int)fminf(fmaxf(ceilf(in_y), 0.0f), Hm1);
        int xc = (int)fminf(fmaxf(ceilf(in_x), 0.0f), Hm1);

        const float4* r0 = fm_b + y0 * rowstride + cq;
        const float4* r1 = fm_b + yc * rowstride + cq;
        int o0 = x0 * NQ;
        int oc = xc * NQ;
        float4 tl = __ldg(r0 + o0);
        float4 tr = __ldg(r0 + oc);
        float4 bl = __ldg(r1 + o0);
        float4 br = __ldg(r1 + oc);

        float4 top, bot, v;
        top.x = fmaf(tr.x - tl.x, lx, tl.x);
        top.y = fmaf(tr.y - tl.y, lx, tl.y);
        top.z = fmaf(tr.z - tl.z, lx, tl.z);
        top.w = fmaf(tr.w - tl.w, lx, tl.w);
        bot.x = fmaf(br.x - bl.x, lx, bl.x);
        bot.y = fmaf(br.y - bl.y, lx, bl.y);
        bot.z = fmaf(br.z - bl.z, lx, bl.z);
        bot.w = fmaf(br.w - bl.w, lx, bl.w);
        v.x = fmaf(bot.x - top.x, ly, top.x);
        v.y = fmaf(bot.y - top.y, ly, top.y);
        v.z = fmaf(bot.z - top.z, ly, top.z);
        v.w = fmaf(bot.w - top.w, ly, top.w);

        float4 res;
        res.x = valid ? v.x : 0.0f;
        res.y = valid ? v.y : 0.0f;
        res.z = valid ? v.z : 0.0f;
        res.w = valid ? v.w : 0.0f;
        out_roi[cell * NQ + cq] = res;

        // cell += 8 == (i+1)*7 + (j+1): increment both, then wrap j
        i += 1;
        j += 1;
        if (j >= OUT_SZ) { j -= OUT_SZ; i += 1; }
    }
}

extern "C" void kernel_launch(void* const* d_in, const int* in_sizes, int n_in,
                              void* d_out, int out_size)
{
    const float* p2   = (const float*)d_in[0];
    const float* p3   = (const float*)d_in[1];
    const float* p4   = (const float*)d_in[2];
    const float* p5   = (const float*)d_in[3];
    const float* rois = (const float*)d_in[4];
    float* out = (float*)d_out;
    int n_rois = in_sizes[4] / 5;

    roialign_kernel<<<n_rois, NTHREADS>>>(p2, p3, p4, p5, rois, out);
}